// round 15
// baseline (speedup 1.0000x reference)
#include <cuda_runtime.h>
#include <cuda_bf16.h>
#include <stdint.h>
#include <math.h>

#define TT 256
#define BB 128
#define EE 512
#define HH 1024
#define G3 3072
#define KC 32            // K per stage
#define NSTG 32          // full K sweep = 32 stages
#define SA 80            // smem row stride bytes (32 bf16 = 64B + 16B pad)

// step kernel per-stage frame (bytes). l1 layout; l0 overlays a subset.
#define FRAME  35840
#define DEPTH  3
#define SMEM_DYN (DEPTH*FRAME)   // 107520

// gi0 fused frame: Ahi 0, Alo 5120, Bhi 10240, Blo 15360
#define GFRAME 20480
#define GSMEM  (3*GFRAME)        // 61440 (dynamic)

// ---------------- device scratch (bss) ----------------
__device__ float g_GI0[(size_t)TT * BB * G3];
__device__ float g_h0f[2][BB * HH];
__device__ float g_h1f[2][BB * HH];
__device__ __nv_bfloat16 g_h0hi[2][BB*HH], g_h0lo[2][BB*HH];
__device__ __nv_bfloat16 g_h1hi[2][BB*HH], g_h1lo[2][BB*HH];
__device__ __nv_bfloat16 g_x1hi[2][BB*HH], g_x1lo[2][BB*HH];
__device__ __nv_bfloat16 g_Whi[3][(size_t)G3*HH];   // 0=Whh0 1=Wih1 2=Whh1
__device__ __nv_bfloat16 g_Wlo[3][(size_t)G3*HH];
__device__ __nv_bfloat16 g_W0hi[(size_t)G3*EE], g_W0lo[(size_t)G3*EE];   // Wih0
__device__ __nv_bfloat16 g_x0hi[(size_t)TT*BB*EE], g_x0lo[(size_t)TT*BB*EE];
// K-split donation buffers: 96 pairs x 256 threads x 24 floats
__device__ float g_part[96][256][24];
__device__ int   g_sflag[96];

// ---------------- helpers ----------------
__device__ __forceinline__ void cpa16(uint32_t dst, const void* src){
    asm volatile("cp.async.cg.shared.global [%0], [%1], 16;" :: "r"(dst), "l"(src));
}
__device__ __forceinline__ void cpa_commit(){ asm volatile("cp.async.commit_group;"); }
__device__ __forceinline__ void cpa_wait1(){ asm volatile("cp.async.wait_group 1;"); }

__device__ __forceinline__ void ldsm4(uint32_t* r, uint32_t a){
    asm volatile("ldmatrix.sync.aligned.m8n8.x4.shared.b16 {%0,%1,%2,%3}, [%4];"
        : "=r"(r[0]),"=r"(r[1]),"=r"(r[2]),"=r"(r[3]) : "r"(a));
}

#define MMA16816(c, a, b0, b1) \
    asm volatile("mma.sync.aligned.m16n8k16.row.col.f32.bf16.bf16.f32 " \
        "{%0,%1,%2,%3},{%4,%5,%6,%7},{%8,%9},{%0,%1,%2,%3};" \
        : "+f"((c)[0]),"+f"((c)[1]),"+f"((c)[2]),"+f"((c)[3]) \
        : "r"((a)[0]),"r"((a)[1]),"r"((a)[2]),"r"((a)[3]),"r"(b0),"r"(b1))

__device__ __forceinline__ float sigf(float v){ return 1.f/(1.f+__expf(-v)); }
__device__ __forceinline__ void split2(float v, __nv_bfloat16& hi, __nv_bfloat16& lo){
    hi = __float2bfloat16(v);
    lo = __float2bfloat16(v - __bfloat162float(hi));
}

// ---------------- init kernels ----------------
__global__ void zero_h_kernel() {
    int i = blockIdx.x*256 + threadIdx.x;  // grid 512 -> 131072 = BB*HH
    if (blockIdx.x == 0 && threadIdx.x < 96) g_sflag[threadIdx.x] = 0;
    g_h0f[0][i]=0.f; g_h1f[0][i]=0.f;
    __nv_bfloat16 z = __float2bfloat16(0.f);
    g_h0hi[0][i]=z; g_h0lo[0][i]=z; g_h1hi[0][i]=z; g_h1lo[0][i]=z;
}
__global__ void split_w_kernel(const float* __restrict__ w0, const float* __restrict__ w1,
                               const float* __restrict__ w2) {
    size_t i = (size_t)blockIdx.x*256 + threadIdx.x;
    int m = blockIdx.y;
    const float* s = (m==0)? w0 : (m==1)? w1 : w2;
    __nv_bfloat16 hi, lo; split2(s[i], hi, lo);
    g_Whi[m][i]=hi; g_Wlo[m][i]=lo;
}
__global__ void split_w0_kernel(const float* __restrict__ w) {
    size_t i = (size_t)blockIdx.x*256 + threadIdx.x;   // grid 6144
    __nv_bfloat16 hi, lo; split2(w[i], hi, lo);
    g_W0hi[i]=hi; g_W0lo[i]=lo;
}
__global__ void split_x_kernel(const float* __restrict__ x) {
    size_t i = (size_t)blockIdx.x*256 + threadIdx.x;   // grid 65536
    __nv_bfloat16 hi, lo; split2(x[i], hi, lo);
    g_x0hi[i]=hi; g_x0lo[i]=lo;
}

// ---------------- GI0 via FUSED split-bf16 mma (R14-proven) ----------------
__global__ __launch_bounds__(128) void gi0_mma(
    const float* __restrict__ bias, const int* __restrict__ bs)
{
    extern __shared__ __align__(16) char smem[];
    const int nbase = blockIdx.x * 64;
    const int trow = blockIdx.y;
    const int t = trow >> 1, mb = (trow & 1) << 6;
    if (mb >= bs[t]) return;
    const int tid = threadIdx.x, wid = tid>>5, lane = tid&31;
    const int l4 = lane>>2, lm4 = lane&3;
    const size_t rowbase = (size_t)(t*BB + mb);

    float cc[8][4];
#pragma unroll
    for (int i=0;i<8;i++)
#pragma unroll
        for (int j=0;j<4;j++) cc[i][j]=0.f;

    const uint32_t smem_u = (uint32_t)__cvta_generic_to_shared(smem);
    const uint32_t a_off = (uint32_t)((wid*16 + (lane&15))*SA + (lane>>4)*16);
    const uint32_t b_off = (uint32_t)(((lane&7) + ((lane>>4)&1)*8)*SA + ((lane>>3)&1)*16);

    auto load_stage = [&](int s){
        const int k0 = s * KC;
        const uint32_t st = smem_u + (s % 3) * GFRAME;
#pragma unroll
        for (int i = 0; i < 4; i++) {
            int cid = tid + i*128, tile = cid>>8, rr = cid&255;
            int r = rr>>2, c = rr&3;
            const __nv_bfloat16* A = tile ? g_x0lo : g_x0hi;
            cpa16(st + tile*5120 + r*SA + c*16, A + (rowbase+r)*EE + k0 + c*8);
        }
#pragma unroll
        for (int i = 0; i < 4; i++) {
            int cid = tid + i*128, tile = cid>>8, rr = cid&255;
            int r = rr>>2, c = rr&3;
            const __nv_bfloat16* W = tile ? g_W0lo : g_W0hi;
            cpa16(st + 10240 + tile*5120 + r*SA + c*16, W + (size_t)(nbase+r)*EE + k0 + c*8);
        }
    };

    load_stage(0); cpa_commit();
    load_stage(1); cpa_commit();
    for (int s = 0; s < 16; s++) {
        cpa_wait1();
        __syncthreads();
        const uint32_t st = smem_u + (s % 3) * GFRAME;
        const uint32_t aH = st + a_off;
        const uint32_t aL = st + 5120 + a_off;
#pragma unroll
        for (int kc = 0; kc < 2; kc++) {
            uint32_t ah[4], al[4];
            ldsm4(ah, aH + kc*32);
            ldsm4(al, aL + kc*32);
#pragma unroll
            for (int g = 0; g < 4; g++) {
                uint32_t bh[4], bl[4];
                uint32_t bgo = (uint32_t)(g*16*SA) + b_off + kc*32;
                ldsm4(bh, st + 10240 + bgo);
                ldsm4(bl, st + 15360 + bgo);
                MMA16816(cc[2*g],   ah, bh[0], bh[1]);
                MMA16816(cc[2*g+1], ah, bh[2], bh[3]);
                MMA16816(cc[2*g],   ah, bl[0], bl[1]);
                MMA16816(cc[2*g+1], ah, bl[2], bl[3]);
                MMA16816(cc[2*g],   al, bh[0], bh[1]);
                MMA16816(cc[2*g+1], al, bh[2], bh[3]);
            }
        }
        if (s+2 < 16) load_stage(s+2);
        cpa_commit();
    }

#pragma unroll
    for (int nt = 0; nt < 8; nt++) {
        int n = nbase + nt*8 + lm4*2;
        float2 bv = *(const float2*)&bias[n];
#pragma unroll
        for (int rr = 0; rr < 2; rr++) {
            size_t row = rowbase + wid*16 + l4 + rr*8;
            float2 o; o.x = cc[nt][rr*2] + bv.x; o.y = cc[nt][rr*2+1] + bv.y;
            *(float2*)&g_GI0[row*G3 + n] = o;
        }
    }
}

// ---------------- fused-pass mma step with K-split donation ----------------
// CTAs [0,64):   layer0 @ t=kk : M64 x 32 hidden cols
// CTAs [64,192): layer1 @ t=kk-1 : M64 x 16 hidden cols, dual GEMM (warp-split)
// When bs[t] <= 64: odd-idx CTA computes K[512:1024) of the even partner's tile.
// R15: partner's inactive-tile pass-through moved AFTER the publish so it no
// longer delays the owner's acquire-spin.
__global__ __launch_bounds__(256, 2) void mma_step(
    const float* __restrict__ bhh0, const float* __restrict__ bih1,
    const float* __restrict__ bhh1, const int* __restrict__ bs, int kk)
{
    extern __shared__ __align__(16) char smem[];
    const int cta = blockIdx.x;
    const bool l1 = cta >= 64;
    const int t = l1 ? kk-1 : kk;
    if (t < 0 || t >= TT) return;
    const int p = t & 1;
    const int idx = l1 ? cta-64 : cta;
    const int jbase = l1 ? (idx>>1)*16 : (idx>>1)*32;
    const int mbase = (idx&1)*64;
    const int tid = threadIdx.x, wid = tid>>5, lane = tid&31;
    const int l4 = lane>>2, lm4 = lane&3;
    const int mi = wid & 3;
    const int ws = wid >> 2;            // l0: n-half ; l1: gemm select (0=gh,1=gi)
    const int active = bs[t];
    const int NCOL = l1 ? 16 : 32;
    const int pid = cta >> 1;           // pair id 0..95

    const bool split   = (active <= 64);
    const bool partner = split && (idx & 1);   // donates K-half to even neighbor
    const int  mbase_c = split ? 0 : mbase;    // compute m-tile

    const float* hpf_all = l1 ? g_h1f[p] : g_h0f[p];
    float* hnf_all = l1 ? g_h1f[p^1] : g_h0f[p^1];
    __nv_bfloat16* hhi_all = l1 ? g_h1hi[p^1] : g_h0hi[p^1];
    __nv_bfloat16* hlo_all = l1 ? g_h1lo[p^1] : g_h0lo[p^1];

    const __nv_bfloat16 *AhHi, *AhLo, *WhHi, *WhLo, *AiHi, *AiLo, *WiHi, *WiLo;
    if (!l1) {
        AhHi = g_h0hi[p]; AhLo = g_h0lo[p]; WhHi = g_Whi[0]; WhLo = g_Wlo[0];
        AiHi = AiLo = WiHi = WiLo = nullptr;
    } else {
        AhHi = g_h1hi[p]; AhLo = g_h1lo[p]; WhHi = g_Whi[2]; WhLo = g_Wlo[2];
        AiHi = g_x1hi[p]; AiLo = g_x1lo[p]; WiHi = g_Whi[1]; WiLo = g_Wlo[1];
    }

    const uint32_t smem_u = (uint32_t)__cvta_generic_to_shared(smem);

    auto load_stage = [&](int s){
        const int k0 = s * KC;
        const uint32_t st = smem_u + (s % DEPTH) * FRAME;
        if (!l1) {
#pragma unroll
            for (int i = 0; i < 2; i++) {
                int cid = tid + i*256, tile = cid>>8, rr = cid&255;
                int r = rr>>2, c = rr&3;
                const __nv_bfloat16* A = tile ? AhLo : AhHi;
                cpa16(st + tile*5120 + r*SA + c*16, A + (size_t)(mbase_c+r)*HH + k0 + c*8);
            }
#pragma unroll
            for (int i = 0; i < 3; i++) {
                int cid = tid + i*256, tile = cid/384, rr = cid%384;
                int r = rr>>2, c = rr&3;
                int wrow = (r>>5)*HH + jbase + (r&31);
                const __nv_bfloat16* W = tile ? WhLo : WhHi;
                cpa16(st + 10240 + tile*7680 + r*SA + c*16, W + (size_t)wrow*HH + k0 + c*8);
            }
        } else {
#pragma unroll
            for (int i = 0; i < 4; i++) {
                int cid = tid + i*256, tile = cid>>8, rr = cid&255;
                int r = rr>>2, c = rr&3;
                const __nv_bfloat16* A = (tile==0)? AhHi : (tile==1)? AhLo
                                       : (tile==2)? AiHi : AiLo;
                cpa16(st + tile*5120 + r*SA + c*16, A + (size_t)(mbase_c+r)*HH + k0 + c*8);
            }
#pragma unroll
            for (int i = 0; i < 3; i++) {
                int cid = tid + i*256, tile = cid/192, rr = cid%192;
                int r = rr>>2, c = rr&3;
                int wrow = (r>>4)*HH + jbase + (r&15);
                const __nv_bfloat16* W = (tile==0)? WhHi : (tile==1)? WhLo
                                       : (tile==2)? WiHi : WiLo;
                cpa16(st + 20480 + tile*3840 + r*SA + c*16, W + (size_t)wrow*HH + k0 + c*8);
            }
        }
    };

    float acc[6][4];
#pragma unroll
    for (int i=0;i<6;i++)
#pragma unroll
        for (int j=0;j<4;j++) acc[i][j]=0.f;

    const uint32_t a_off = (uint32_t)((mi*16 + (lane&15))*SA + (lane>>4)*16);
    const uint32_t b_off = (uint32_t)(((lane&7) + ((lane>>4)&1)*8)*SA + ((lane>>3)&1)*16);

    // stage range: owner of a split pair does K[0:512), partner K[512:1024)
    const int sBeg = partner ? (NSTG/2) : 0;
    const int sEnd = (split && !partner) ? (NSTG/2) : NSTG;

    load_stage(sBeg);   cpa_commit();
    load_stage(sBeg+1); cpa_commit();
    for (int s = sBeg; s < sEnd; s++) {
        cpa_wait1();
        __syncthreads();
        const uint32_t st = smem_u + (s % DEPTH) * FRAME;
        if (!l1) {
            const uint32_t aH = st + a_off;
            const uint32_t aL = st + 5120 + a_off;
            const uint32_t grp = (uint32_t)(ws*16*SA);
#pragma unroll
            for (int kc = 0; kc < 2; kc++) {
                uint32_t ah[4], al[4];
                ldsm4(ah, aH + kc*32);
                ldsm4(al, aL + kc*32);
#pragma unroll
                for (int g = 0; g < 3; g++) {
                    uint32_t bh[4], bl[4];
                    uint32_t bgo = (uint32_t)(g*32*SA) + grp + b_off + kc*32;
                    ldsm4(bh, st + 10240 + bgo);
                    ldsm4(bl, st + 17920 + bgo);
                    MMA16816(acc[2*g],   ah, bh[0], bh[1]);
                    MMA16816(acc[2*g+1], ah, bh[2], bh[3]);
                    MMA16816(acc[2*g],   ah, bl[0], bl[1]);
                    MMA16816(acc[2*g+1], ah, bl[2], bl[3]);
                    MMA16816(acc[2*g],   al, bh[0], bh[1]);
                    MMA16816(acc[2*g+1], al, bh[2], bh[3]);
                }
            }
        } else {
            const uint32_t aH = st + (ws?10240:0) + a_off;
            const uint32_t aL = aH + 5120;
            const uint32_t bHbase = st + 20480 + (ws?7680:0);
#pragma unroll
            for (int kc = 0; kc < 2; kc++) {
                uint32_t ah[4], al[4];
                ldsm4(ah, aH + kc*32);
                ldsm4(al, aL + kc*32);
#pragma unroll
                for (int g = 0; g < 3; g++) {
                    uint32_t bh[4], bl[4];
                    uint32_t bgo = (uint32_t)(g*16*SA) + b_off + kc*32;
                    ldsm4(bh, bHbase + bgo);
                    ldsm4(bl, bHbase + 3840 + bgo);
                    MMA16816(acc[2*g],   ah, bh[0], bh[1]);
                    MMA16816(acc[2*g+1], ah, bh[2], bh[3]);
                    MMA16816(acc[2*g],   ah, bl[0], bl[1]);
                    MMA16816(acc[2*g+1], ah, bl[2], bl[3]);
                    MMA16816(acc[2*g],   al, bh[0], bh[1]);
                    MMA16816(acc[2*g+1], al, bh[2], bh[3]);
                }
            }
        }
        if (s+2 < sEnd) load_stage(s+2);
        cpa_commit();
    }

    // ---- partner: publish raw accumulators FIRST, then pass-through ----
    if (partner) {
        float* dst = &g_part[pid][tid][0];
#pragma unroll
        for (int i = 0; i < 6; i++)
#pragma unroll
            for (int j = 0; j < 4; j++) dst[i*4+j] = acc[i][j];
        __threadfence();
        __syncthreads();
        if (tid == 0) {
            int v = kk + 1;
            asm volatile("st.release.gpu.s32 [%0], %1;" :: "l"(&g_sflag[pid]), "r"(v) : "memory");
        }
        // pass-through for my own inactive m-tile (rows 64..127), off the owner's
        // critical path; only consumed by the NEXT kernel launch.
        const int tot = 64*NCOL;
        for (int i = tid; i < tot; i += 256) {
            int r = i / NCOL, c = i % NCOL;
            size_t off = (size_t)(64 + r)*HH + jbase + c;
            float hv = hpf_all[off];
            hnf_all[off] = hv;
            __nv_bfloat16 hi, lo; split2(hv, hi, lo);
            hhi_all[off] = hi; hlo_all[off] = lo;
        }
        return;
    }

    // ---- l1: exchange gi accumulators to gh warps via smem ----
    float ci[6][4];
    if (l1) {
        __syncthreads();   // ensure no warp still reads the frame smem bytes
        float* xch = (float*)smem;
        if (ws == 1) {
            float* dst = xch + (size_t)(mi*32 + lane)*24;
#pragma unroll
            for (int i = 0; i < 6; i++)
#pragma unroll
                for (int j = 0; j < 4; j++) dst[i*4+j] = acc[i][j];
        }
        __syncthreads();
        if (ws == 0) {
            const float* src = xch + (size_t)(mi*32 + lane)*24;
#pragma unroll
            for (int i = 0; i < 6; i++)
#pragma unroll
                for (int j = 0; j < 4; j++) ci[i][j] = src[i*4+j];
        } else {
            return;   // gi warps done
        }
    }

    // ---- split owner: wait for partner's K-half and fold it in ----
    if (split) {
        const int tgt = kk + 1;
        int v;
        do {
            asm volatile("ld.acquire.gpu.s32 %0, [%1];" : "=r"(v)
                         : "l"((const int*)&g_sflag[pid]) : "memory");
        } while (v < tgt);
        const float* ph = &g_part[pid][tid][0];
#pragma unroll
        for (int i = 0; i < 6; i++)
#pragma unroll
            for (int j = 0; j < 4; j++) acc[i][j] += ph[i*4+j];
        if (l1) {
            const float* pi2 = &g_part[pid][tid+128][0];
#pragma unroll
            for (int i = 0; i < 6; i++)
#pragma unroll
                for (int j = 0; j < 4; j++) ci[i][j] += pi2[i*4+j];
        }
    }

    // ---- epilogue (R8-proven gate math), rows mbase_c..mbase_c+63 ----
    const int m0 = mbase_c + mi*16 + l4;
    const int jw = l1 ? jbase : (jbase + ws*16);
    const float* bh = l1 ? bhh1 : bhh0;
#pragma unroll
    for (int c = 0; c < 2; c++) {
        const int j = jw + c*8 + lm4*2;
        float2 bhr = *(const float2*)(bh + j);
        float2 bhz = *(const float2*)(bh + HH + j);
        float2 bhn = *(const float2*)(bh + 2*HH + j);
        float2 bir, biz, bin;
        if (l1) {
            bir = *(const float2*)(bih1 + j);
            biz = *(const float2*)(bih1 + HH + j);
            bin = *(const float2*)(bih1 + 2*HH + j);
        }
        const int rg = c, zg = 2 + c, ng = 4 + c;
#pragma unroll
        for (int rr = 0; rr < 2; rr++) {
            const int m = m0 + rr*8;
            const bool keep = m < active;
            float gr0,gr1,gz0,gz1,gn0,gn1;
            if (!l1) {
                const float* gp = g_GI0 + (size_t)(t*BB + m)*G3;
                float2 a = *(const float2*)(gp + j);
                float2 b = *(const float2*)(gp + HH + j);
                float2 cc2 = *(const float2*)(gp + 2*HH + j);
                gr0=a.x; gr1=a.y; gz0=b.x; gz1=b.y; gn0=cc2.x; gn1=cc2.y;
            } else {
                gr0 = ci[rg][rr*2] + bir.x;  gr1 = ci[rg][rr*2+1] + bir.y;
                gz0 = ci[zg][rr*2] + biz.x;  gz1 = ci[zg][rr*2+1] + biz.y;
                gn0 = ci[ng][rr*2] + bin.x;  gn1 = ci[ng][rr*2+1] + bin.y;
            }
            float hr0 = acc[rg][rr*2] + bhr.x, hr1 = acc[rg][rr*2+1] + bhr.y;
            float hz0 = acc[zg][rr*2] + bhz.x, hz1 = acc[zg][rr*2+1] + bhz.y;
            float hn0 = acc[ng][rr*2] + bhn.x, hn1 = acc[ng][rr*2+1] + bhn.y;

            size_t off = (size_t)m*HH + j;
            float2 hp = *(const float2*)(hpf_all + off);

            float r0 = sigf(gr0+hr0), z0 = sigf(gz0+hz0);
            float nv0 = tanhf(fmaf(r0, hn0, gn0));
            float hv0 = fmaf(z0, hp.x - nv0, nv0);
            float r1 = sigf(gr1+hr1), z1 = sigf(gz1+hz1);
            float nv1 = tanhf(fmaf(r1, hn1, gn1));
            float hv1 = fmaf(z1, hp.y - nv1, nv1);

            float kv0 = keep ? hv0 : hp.x;
            float kv1 = keep ? hv1 : hp.y;

            float2 outv; outv.x = kv0; outv.y = kv1;
            *(float2*)(hnf_all + off) = outv;
            __nv_bfloat162 vhi, vlo;
            split2(kv0, vhi.x, vlo.x);
            split2(kv1, vhi.y, vlo.y);
            *(__nv_bfloat162*)(hhi_all + off) = vhi;
            *(__nv_bfloat162*)(hlo_all + off) = vlo;
            if (!l1) {
                __nv_bfloat162 xh, xl;
                split2(hv0, xh.x, xl.x);
                split2(hv1, xh.y, xl.y);
                *(__nv_bfloat162*)(g_x1hi[p] + off) = xh;
                *(__nv_bfloat162*)(g_x1lo[p] + off) = xl;
            }
        }
    }
}

// ---------------- final gather ----------------
__global__ void gather_kernel(const int* __restrict__ u, float* __restrict__ out) {
    int idx = blockIdx.x*blockDim.x + threadIdx.x;
    int l = idx / (BB*(HH/4));
    int rem = idx % (BB*(HH/4));
    int b = rem / (HH/4), j4 = rem % (HH/4);
    const float* src = (l ? g_h1f[0] : g_h0f[0]) + (size_t)u[b]*HH;
    ((float4*)out)[idx] = ((const float4*)src)[j4];
}

// ---------------------------------------------------------------------------
extern "C" void kernel_launch(void* const* d_in, const int* in_sizes, int n_in,
                              void* d_out, int out_size) {
    const float* x    = (const float*)d_in[0];
    const float* Wih0 = (const float*)d_in[1];
    const float* Whh0 = (const float*)d_in[2];
    const float* bih0 = (const float*)d_in[3];
    const float* bhh0 = (const float*)d_in[4];
    const float* Wih1 = (const float*)d_in[5];
    const float* Whh1 = (const float*)d_in[6];
    const float* bih1 = (const float*)d_in[7];
    const float* bhh1 = (const float*)d_in[8];
    const int*   bs   = (const int*)d_in[9];
    const int*   ui   = (const int*)d_in[10];

    cudaFuncSetAttribute(mma_step, cudaFuncAttributeMaxDynamicSharedMemorySize, SMEM_DYN);
    cudaFuncSetAttribute(gi0_mma, cudaFuncAttributeMaxDynamicSharedMemorySize, GSMEM);

    zero_h_kernel<<<512, 256>>>();
    split_w_kernel<<<dim3((G3*HH)/256, 3), 256>>>(Whh0, Wih1, Whh1);
    split_w0_kernel<<<(G3*EE)/256, 256>>>(Wih0);
    split_x_kernel<<<(TT*BB*EE)/256, 256>>>(x);
    gi0_mma<<<dim3(48, 2*TT), 128, GSMEM>>>(bih0, bs);
    for (int k = 0; k <= TT; k++)
        mma_step<<<192, 256, SMEM_DYN>>>(bhh0, bih1, bhh1, bs, k);
    gather_kernel<<<256, 256>>>(ui, (float*)d_out);
}

// round 16
// speedup vs baseline: 1.2110x; 1.2110x over previous
#include <cuda_runtime.h>
#include <cuda_fp16.h>
#include <stdint.h>
#include <math.h>

#define TT 256
#define BB 128
#define EE 512
#define HH 1024
#define G3 3072
#define KC 32            // K per stage
#define NSTG 32          // full K sweep = 32 stages
#define SA 80            // smem row stride bytes (32 fp16 = 64B + 16B pad)

// step kernel per-stage frame (bytes).
//  l0: A 0 (5120), Bhi 5120 (7680), Blo 12800 (7680)            -> 20480
//  l1: AH 0 (5120), AI 5120 (5120),
//      B @10240: [WHhi 3840][WHlo 3840][WIhi 3840][WIlo 3840]   -> 25600
#define FRAME  25600
#define DEPTH  3
#define SMEM_DYN (DEPTH*FRAME)   // 76800

// gi0 frame: A 0 (5120), Bhi 5120 (5120), Blo 10240 (5120)
#define GFRAME 15360
#define GSMEM  (3*GFRAME)        // 46080

// ---------------- device scratch (bss) ----------------
__device__ float g_GI0[(size_t)TT * BB * G3];
__device__ float g_h0f[2][BB * HH];
__device__ float g_h1f[2][BB * HH];
__device__ __half g_h0h[2][BB*HH];              // fp16 state (single precision level)
__device__ __half g_h1h[2][BB*HH];
__device__ __half g_x1h[2][BB*HH];
__device__ __half g_Whi[3][(size_t)G3*HH];      // 0=Whh0 1=Wih1 2=Whh1 (hi+lo split)
__device__ __half g_Wlo[3][(size_t)G3*HH];
__device__ __half g_W0hi[(size_t)G3*EE], g_W0lo[(size_t)G3*EE];   // Wih0
__device__ __half g_x0h[(size_t)TT*BB*EE];
// K-split donation buffers: 96 pairs x 256 threads x 24 floats
__device__ float g_part[96][256][24];
__device__ int   g_sflag[96];

// ---------------- helpers ----------------
__device__ __forceinline__ void cpa16(uint32_t dst, const void* src){
    asm volatile("cp.async.cg.shared.global [%0], [%1], 16;" :: "r"(dst), "l"(src));
}
__device__ __forceinline__ void cpa_commit(){ asm volatile("cp.async.commit_group;"); }
__device__ __forceinline__ void cpa_wait1(){ asm volatile("cp.async.wait_group 1;"); }

__device__ __forceinline__ void ldsm4(uint32_t* r, uint32_t a){
    asm volatile("ldmatrix.sync.aligned.m8n8.x4.shared.b16 {%0,%1,%2,%3}, [%4];"
        : "=r"(r[0]),"=r"(r[1]),"=r"(r[2]),"=r"(r[3]) : "r"(a));
}

#define MMA16816(c, a, b0, b1) \
    asm volatile("mma.sync.aligned.m16n8k16.row.col.f32.f16.f16.f32 " \
        "{%0,%1,%2,%3},{%4,%5,%6,%7},{%8,%9},{%0,%1,%2,%3};" \
        : "+f"((c)[0]),"+f"((c)[1]),"+f"((c)[2]),"+f"((c)[3]) \
        : "r"((a)[0]),"r"((a)[1]),"r"((a)[2]),"r"((a)[3]),"r"(b0),"r"(b1))

__device__ __forceinline__ float sigf(float v){ return 1.f/(1.f+__expf(-v)); }
__device__ __forceinline__ void split2h(float v, __half& hi, __half& lo){
    hi = __float2half_rn(v);
    lo = __float2half_rn(v - __half2float(hi));
}

// ---------------- init kernels ----------------
__global__ void zero_h_kernel() {
    int i = blockIdx.x*256 + threadIdx.x;  // grid 512 -> 131072 = BB*HH
    if (blockIdx.x == 0 && threadIdx.x < 96) g_sflag[threadIdx.x] = 0;
    g_h0f[0][i]=0.f; g_h1f[0][i]=0.f;
    __half z = __float2half(0.f);
    g_h0h[0][i]=z; g_h1h[0][i]=z;
}
__global__ void split_w_kernel(const float* __restrict__ w0, const float* __restrict__ w1,
                               const float* __restrict__ w2) {
    size_t i = (size_t)blockIdx.x*256 + threadIdx.x;
    int m = blockIdx.y;
    const float* s = (m==0)? w0 : (m==1)? w1 : w2;
    __half hi, lo; split2h(s[i], hi, lo);
    g_Whi[m][i]=hi; g_Wlo[m][i]=lo;
}
__global__ void split_w0_kernel(const float* __restrict__ w) {
    size_t i = (size_t)blockIdx.x*256 + threadIdx.x;   // grid 6144
    __half hi, lo; split2h(w[i], hi, lo);
    g_W0hi[i]=hi; g_W0lo[i]=lo;
}
__global__ void split_x_kernel(const float* __restrict__ x) {
    size_t i = (size_t)blockIdx.x*256 + threadIdx.x;   // grid 65536
    g_x0h[i] = __float2half_rn(x[i]);
}

// ---------------- GI0 via 2-stream fp16 mma ----------------
// grid (48, 512): x = 64-col block of G3 ; y = t*2 + mhalf. CTA = M64 x N64.
__global__ __launch_bounds__(128) void gi0_mma(
    const float* __restrict__ bias, const int* __restrict__ bs)
{
    extern __shared__ __align__(16) char smem[];
    const int nbase = blockIdx.x * 64;
    const int trow = blockIdx.y;
    const int t = trow >> 1, mb = (trow & 1) << 6;
    if (mb >= bs[t]) return;
    const int tid = threadIdx.x, wid = tid>>5, lane = tid&31;
    const int l4 = lane>>2, lm4 = lane&3;
    const size_t rowbase = (size_t)(t*BB + mb);

    float cc[8][4];
#pragma unroll
    for (int i=0;i<8;i++)
#pragma unroll
        for (int j=0;j<4;j++) cc[i][j]=0.f;

    const uint32_t smem_u = (uint32_t)__cvta_generic_to_shared(smem);
    const uint32_t a_off = (uint32_t)((wid*16 + (lane&15))*SA + (lane>>4)*16);
    const uint32_t b_off = (uint32_t)(((lane&7) + ((lane>>4)&1)*8)*SA + ((lane>>3)&1)*16);

    auto load_stage = [&](int s){
        const int k0 = s * KC;
        const uint32_t st = smem_u + (s % 3) * GFRAME;
        // A: 64 rows x 4 chunks = 256 cpa16 (2/thread)
#pragma unroll
        for (int i = 0; i < 2; i++) {
            int cid = tid + i*128, r = cid>>2, c = cid&3;
            cpa16(st + r*SA + c*16, g_x0h + (rowbase+r)*EE + k0 + c*8);
        }
        // B: hi+lo tiles, 64 rows x 4 chunks each = 512 cpa16 (4/thread)
#pragma unroll
        for (int i = 0; i < 4; i++) {
            int cid = tid + i*128, tile = cid>>8, rr = cid&255;
            int r = rr>>2, c = rr&3;
            const __half* W = tile ? g_W0lo : g_W0hi;
            cpa16(st + 5120 + tile*5120 + r*SA + c*16, W + (size_t)(nbase+r)*EE + k0 + c*8);
        }
    };

    load_stage(0); cpa_commit();
    load_stage(1); cpa_commit();
    for (int s = 0; s < 16; s++) {
        cpa_wait1();
        __syncthreads();
        const uint32_t st = smem_u + (s % 3) * GFRAME;
        const uint32_t aB = st + a_off;
#pragma unroll
        for (int kc = 0; kc < 2; kc++) {
            uint32_t a[4];
            ldsm4(a, aB + kc*32);
#pragma unroll
            for (int g = 0; g < 4; g++) {
                uint32_t bh[4], bl[4];
                uint32_t bgo = (uint32_t)(g*16*SA) + b_off + kc*32;
                ldsm4(bh, st + 5120 + bgo);
                ldsm4(bl, st + 10240 + bgo);
                MMA16816(cc[2*g],   a, bh[0], bh[1]);
                MMA16816(cc[2*g+1], a, bh[2], bh[3]);
                MMA16816(cc[2*g],   a, bl[0], bl[1]);
                MMA16816(cc[2*g+1], a, bl[2], bl[3]);
            }
        }
        if (s+2 < 16) load_stage(s+2);
        cpa_commit();
    }

#pragma unroll
    for (int nt = 0; nt < 8; nt++) {
        int n = nbase + nt*8 + lm4*2;
        float2 bv = *(const float2*)&bias[n];
#pragma unroll
        for (int rr = 0; rr < 2; rr++) {
            size_t row = rowbase + wid*16 + l4 + rr*8;
            float2 o; o.x = cc[nt][rr*2] + bv.x; o.y = cc[nt][rr*2+1] + bv.y;
            *(float2*)&g_GI0[row*G3 + n] = o;
        }
    }
}

// ---------------- 2-stream fp16 mma step with K-split donation ----------------
// CTAs [0,64):   layer0 @ t=kk : M64 x 32 hidden cols
// CTAs [64,192): layer1 @ t=kk-1 : M64 x 16 hidden cols, dual GEMM (warp-split)
// When bs[t] <= 64: odd-idx CTA computes K[512:1024) of the even partner's tile.
__global__ __launch_bounds__(256, 2) void mma_step(
    const float* __restrict__ bhh0, const float* __restrict__ bih1,
    const float* __restrict__ bhh1, const int* __restrict__ bs, int kk)
{
    extern __shared__ __align__(16) char smem[];
    const int cta = blockIdx.x;
    const bool l1 = cta >= 64;
    const int t = l1 ? kk-1 : kk;
    if (t < 0 || t >= TT) return;
    const int p = t & 1;
    const int idx = l1 ? cta-64 : cta;
    const int jbase = l1 ? (idx>>1)*16 : (idx>>1)*32;
    const int mbase = (idx&1)*64;
    const int tid = threadIdx.x, wid = tid>>5, lane = tid&31;
    const int l4 = lane>>2, lm4 = lane&3;
    const int mi = wid & 3;
    const int ws = wid >> 2;            // l0: n-half ; l1: gemm select (0=gh,1=gi)
    const int active = bs[t];
    const int NCOL = l1 ? 16 : 32;
    const int pid = cta >> 1;           // pair id 0..95

    const bool split   = (active <= 64);
    const bool partner = split && (idx & 1);   // donates K-half to even neighbor
    const int  mbase_c = split ? 0 : mbase;    // compute m-tile

    const float* hpf_all = l1 ? g_h1f[p] : g_h0f[p];
    float* hnf_all = l1 ? g_h1f[p^1] : g_h0f[p^1];
    __half* hh_all = l1 ? g_h1h[p^1] : g_h0h[p^1];

    if (partner) {
        // my own m-tile (rows 64..127) is inactive: pass h through unchanged
        const int tot = 64*NCOL;
        for (int i = tid; i < tot; i += 256) {
            int r = i / NCOL, c = i % NCOL;
            size_t off = (size_t)(64 + r)*HH + jbase + c;
            float hv = hpf_all[off];
            hnf_all[off] = hv;
            hh_all[off] = __float2half_rn(hv);
        }
        // then fall through: compute partner K-half for rows 0..63
    }

    const __half *Ah, *WhHi, *WhLo, *Ai, *WiHi, *WiLo;
    if (!l1) {
        Ah = g_h0h[p]; WhHi = g_Whi[0]; WhLo = g_Wlo[0];
        Ai = nullptr; WiHi = WiLo = nullptr;
    } else {
        Ah = g_h1h[p]; WhHi = g_Whi[2]; WhLo = g_Wlo[2];
        Ai = g_x1h[p]; WiHi = g_Whi[1]; WiLo = g_Wlo[1];
    }

    const uint32_t smem_u = (uint32_t)__cvta_generic_to_shared(smem);

    auto load_stage = [&](int s){
        const int k0 = s * KC;
        const uint32_t st = smem_u + (s % DEPTH) * FRAME;
        if (!l1) {
            {   // A: 64 rows x 4 chunks = 256 ops (1/thread)
                int r = tid>>2, c = tid&3;
                cpa16(st + r*SA + c*16, Ah + (size_t)(mbase_c+r)*HH + k0 + c*8);
            }
            // B: hi+lo tiles, 96 rows x 4 each = 768 ops (3/thread)
#pragma unroll
            for (int i = 0; i < 3; i++) {
                int cid = tid + i*256, tile = cid/384, rr = cid%384;
                int r = rr>>2, c = rr&3;
                int wrow = (r>>5)*HH + jbase + (r&31);
                const __half* W = tile ? WhLo : WhHi;
                cpa16(st + 5120 + tile*7680 + r*SA + c*16, W + (size_t)wrow*HH + k0 + c*8);
            }
        } else {
            // A: AH + AI tiles, 256 each = 512 ops (2/thread)
#pragma unroll
            for (int i = 0; i < 2; i++) {
                int cid = tid + i*256, tile = cid>>8, rr = cid&255;
                int r = rr>>2, c = rr&3;
                const __half* A = tile ? Ai : Ah;
                cpa16(st + tile*5120 + r*SA + c*16, A + (size_t)(mbase_c+r)*HH + k0 + c*8);
            }
            // B: 4 tiles (WHhi,WHlo,WIhi,WIlo) x 192 = 768 ops (3/thread)
#pragma unroll
            for (int i = 0; i < 3; i++) {
                int cid = tid + i*256, tile = cid/192, rr = cid%192;
                int r = rr>>2, c = rr&3;
                int wrow = (r>>4)*HH + jbase + (r&15);
                const __half* W = (tile==0)? WhHi : (tile==1)? WhLo
                                : (tile==2)? WiHi : WiLo;
                cpa16(st + 10240 + tile*3840 + r*SA + c*16, W + (size_t)wrow*HH + k0 + c*8);
            }
        }
    };

    float acc[6][4];
#pragma unroll
    for (int i=0;i<6;i++)
#pragma unroll
        for (int j=0;j<4;j++) acc[i][j]=0.f;

    const uint32_t a_off = (uint32_t)((mi*16 + (lane&15))*SA + (lane>>4)*16);
    const uint32_t b_off = (uint32_t)(((lane&7) + ((lane>>4)&1)*8)*SA + ((lane>>3)&1)*16);

    // stage range: owner of a split pair does K[0:512), partner K[512:1024)
    const int sBeg = partner ? (NSTG/2) : 0;
    const int sEnd = (split && !partner) ? (NSTG/2) : NSTG;

    load_stage(sBeg);   cpa_commit();
    load_stage(sBeg+1); cpa_commit();
    for (int s = sBeg; s < sEnd; s++) {
        cpa_wait1();
        __syncthreads();
        const uint32_t st = smem_u + (s % DEPTH) * FRAME;
        if (!l1) {
            const uint32_t aB = st + a_off;
            const uint32_t grp = (uint32_t)(ws*16*SA);
#pragma unroll
            for (int kc = 0; kc < 2; kc++) {
                uint32_t a[4];
                ldsm4(a, aB + kc*32);
#pragma unroll
                for (int g = 0; g < 3; g++) {
                    uint32_t bh[4], bl[4];
                    uint32_t bgo = (uint32_t)(g*32*SA) + grp + b_off + kc*32;
                    ldsm4(bh, st + 5120 + bgo);
                    ldsm4(bl, st + 12800 + bgo);
                    MMA16816(acc[2*g],   a, bh[0], bh[1]);
                    MMA16816(acc[2*g+1], a, bh[2], bh[3]);
                    MMA16816(acc[2*g],   a, bl[0], bl[1]);
                    MMA16816(acc[2*g+1], a, bl[2], bl[3]);
                }
            }
        } else {
            const uint32_t aB = st + (ws?5120:0) + a_off;
            const uint32_t bHbase = st + 10240 + (ws?7680:0);
#pragma unroll
            for (int kc = 0; kc < 2; kc++) {
                uint32_t a[4];
                ldsm4(a, aB + kc*32);
#pragma unroll
                for (int g = 0; g < 3; g++) {
                    uint32_t bh[4], bl[4];
                    uint32_t bgo = (uint32_t)(g*16*SA) + b_off + kc*32;
                    ldsm4(bh, bHbase + bgo);
                    ldsm4(bl, bHbase + 3840 + bgo);
                    MMA16816(acc[2*g],   a, bh[0], bh[1]);
                    MMA16816(acc[2*g+1], a, bh[2], bh[3]);
                    MMA16816(acc[2*g],   a, bl[0], bl[1]);
                    MMA16816(acc[2*g+1], a, bl[2], bl[3]);
                }
            }
        }
        if (s+2 < sEnd) load_stage(s+2);
        cpa_commit();
    }

    // ---- partner: publish raw accumulators, signal, done ----
    if (partner) {
        float* dst = &g_part[pid][tid][0];
#pragma unroll
        for (int i = 0; i < 6; i++)
#pragma unroll
            for (int j = 0; j < 4; j++) dst[i*4+j] = acc[i][j];
        __threadfence();
        __syncthreads();
        if (tid == 0) {
            int v = kk + 1;
            asm volatile("st.release.gpu.s32 [%0], %1;" :: "l"(&g_sflag[pid]), "r"(v) : "memory");
        }
        return;
    }

    // ---- l1: exchange gi accumulators to gh warps via smem ----
    float ci[6][4];
    if (l1) {
        __syncthreads();   // ensure no warp still reads the frame smem bytes
        float* xch = (float*)smem;
        if (ws == 1) {
            float* dst = xch + (size_t)(mi*32 + lane)*24;
#pragma unroll
            for (int i = 0; i < 6; i++)
#pragma unroll
                for (int j = 0; j < 4; j++) dst[i*4+j] = acc[i][j];
        }
        __syncthreads();
        if (ws == 0) {
            const float* src = xch + (size_t)(mi*32 + lane)*24;
#pragma unroll
            for (int i = 0; i < 6; i++)
#pragma unroll
                for (int j = 0; j < 4; j++) ci[i][j] = src[i*4+j];
        } else {
            return;   // gi warps done
        }
    }

    // ---- split owner: wait for partner's K-half and fold it in ----
    if (split) {
        const int tgt = kk + 1;
        int v;
        do {
            asm volatile("ld.acquire.gpu.s32 %0, [%1];" : "=r"(v)
                         : "l"((const int*)&g_sflag[pid]) : "memory");
        } while (v < tgt);
        const float* ph = &g_part[pid][tid][0];
#pragma unroll
        for (int i = 0; i < 6; i++)
#pragma unroll
            for (int j = 0; j < 4; j++) acc[i][j] += ph[i*4+j];
        if (l1) {
            const float* pi2 = &g_part[pid][tid+128][0];
#pragma unroll
            for (int i = 0; i < 6; i++)
#pragma unroll
                for (int j = 0; j < 4; j++) ci[i][j] += pi2[i*4+j];
        }
    }

    // ---- epilogue (R8-proven gate math), rows mbase_c..mbase_c+63 ----
    const int m0 = mbase_c + mi*16 + l4;
    const int jw = l1 ? jbase : (jbase + ws*16);
    const float* bh = l1 ? bhh1 : bhh0;
#pragma unroll
    for (int c = 0; c < 2; c++) {
        const int j = jw + c*8 + lm4*2;
        float2 bhr = *(const float2*)(bh + j);
        float2 bhz = *(const float2*)(bh + HH + j);
        float2 bhn = *(const float2*)(bh + 2*HH + j);
        float2 bir, biz, bin;
        if (l1) {
            bir = *(const float2*)(bih1 + j);
            biz = *(const float2*)(bih1 + HH + j);
            bin = *(const float2*)(bih1 + 2*HH + j);
        }
        const int rg = c, zg = 2 + c, ng = 4 + c;
#pragma unroll
        for (int rr = 0; rr < 2; rr++) {
            const int m = m0 + rr*8;
            const bool keep = m < active;
            float gr0,gr1,gz0,gz1,gn0,gn1;
            if (!l1) {
                const float* gp = g_GI0 + (size_t)(t*BB + m)*G3;
                float2 a = *(const float2*)(gp + j);
                float2 b = *(const float2*)(gp + HH + j);
                float2 cc2 = *(const float2*)(gp + 2*HH + j);
                gr0=a.x; gr1=a.y; gz0=b.x; gz1=b.y; gn0=cc2.x; gn1=cc2.y;
            } else {
                gr0 = ci[rg][rr*2] + bir.x;  gr1 = ci[rg][rr*2+1] + bir.y;
                gz0 = ci[zg][rr*2] + biz.x;  gz1 = ci[zg][rr*2+1] + biz.y;
                gn0 = ci[ng][rr*2] + bin.x;  gn1 = ci[ng][rr*2+1] + bin.y;
            }
            float hr0 = acc[rg][rr*2] + bhr.x, hr1 = acc[rg][rr*2+1] + bhr.y;
            float hz0 = acc[zg][rr*2] + bhz.x, hz1 = acc[zg][rr*2+1] + bhz.y;
            float hn0 = acc[ng][rr*2] + bhn.x, hn1 = acc[ng][rr*2+1] + bhn.y;

            size_t off = (size_t)m*HH + j;
            float2 hp = *(const float2*)(hpf_all + off);

            float r0 = sigf(gr0+hr0), z0 = sigf(gz0+hz0);
            float nv0 = tanhf(fmaf(r0, hn0, gn0));
            float hv0 = fmaf(z0, hp.x - nv0, nv0);
            float r1 = sigf(gr1+hr1), z1 = sigf(gz1+hz1);
            float nv1 = tanhf(fmaf(r1, hn1, gn1));
            float hv1 = fmaf(z1, hp.y - nv1, nv1);

            float kv0 = keep ? hv0 : hp.x;
            float kv1 = keep ? hv1 : hp.y;

            float2 outv; outv.x = kv0; outv.y = kv1;
            *(float2*)(hnf_all + off) = outv;
            __half2 vh;
            vh.x = __float2half_rn(kv0);
            vh.y = __float2half_rn(kv1);
            *(__half2*)(hh_all + off) = vh;
            if (!l1) {
                // layer1 input = UNMASKED hn
                __half2 xh;
                xh.x = __float2half_rn(hv0);
                xh.y = __float2half_rn(hv1);
                *(__half2*)(g_x1h[p] + off) = xh;
            }
        }
    }
}

// ---------------- final gather ----------------
__global__ void gather_kernel(const int* __restrict__ u, float* __restrict__ out) {
    int idx = blockIdx.x*blockDim.x + threadIdx.x;
    int l = idx / (BB*(HH/4));
    int rem = idx % (BB*(HH/4));
    int b = rem / (HH/4), j4 = rem % (HH/4);
    const float* src = (l ? g_h1f[0] : g_h0f[0]) + (size_t)u[b]*HH;
    ((float4*)out)[idx] = ((const float4*)src)[j4];
}

// ---------------------------------------------------------------------------
extern "C" void kernel_launch(void* const* d_in, const int* in_sizes, int n_in,
                              void* d_out, int out_size) {
    const float* x    = (const float*)d_in[0];
    const float* Wih0 = (const float*)d_in[1];
    const float* Whh0 = (const float*)d_in[2];
    const float* bih0 = (const float*)d_in[3];
    const float* bhh0 = (const float*)d_in[4];
    const float* Wih1 = (const float*)d_in[5];
    const float* Whh1 = (const float*)d_in[6];
    const float* bih1 = (const float*)d_in[7];
    const float* bhh1 = (const float*)d_in[8];
    const int*   bs   = (const int*)d_in[9];
    const int*   ui   = (const int*)d_in[10];

    cudaFuncSetAttribute(mma_step, cudaFuncAttributeMaxDynamicSharedMemorySize, SMEM_DYN);
    cudaFuncSetAttribute(gi0_mma, cudaFuncAttributeMaxDynamicSharedMemorySize, GSMEM);

    zero_h_kernel<<<512, 256>>>();
    split_w_kernel<<<dim3((G3*HH)/256, 3), 256>>>(Whh0, Wih1, Whh1);
    split_w0_kernel<<<(G3*EE)/256, 256>>>(Wih0);
    split_x_kernel<<<(TT*BB*EE)/256, 256>>>(x);
    gi0_mma<<<dim3(48, 2*TT), 128, GSMEM>>>(bih0, bs);
    for (int k = 0; k <= TT; k++)
        mma_step<<<192, 256, SMEM_DYN>>>(bhh0, bih1, bhh1, bs, k);
    gather_kernel<<<256, 256>>>(ui, (float*)d_out);
}

// round 17
// speedup vs baseline: 1.5618x; 1.2897x over previous
#include <cuda_runtime.h>
#include <cuda_fp16.h>
#include <stdint.h>
#include <math.h>

#define TT 256
#define BB 128
#define EE 512
#define HH 1024
#define G3 3072
#define KC 32            // K per stage
#define NSTG 32          // full K sweep = 32 stages
#define SA 80            // smem row stride bytes (32 fp16 = 64B + 16B pad)

// step kernel per-stage frame (bytes).
//  l0: A 0 (5120), B 5120 (7680)                          -> 12800
//  l1: AH 0 (5120), AI 5120 (5120), WH 10240 (3840), WI 14080 (3840) -> 17920
#define FRAME  17920
#define DEPTH  3
#define SMEM_DYN (DEPTH*FRAME)   // 53760

// gi0 frame: A 0 (5120), B 5120 (5120)
#define GFRAME 10240
#define GSMEM  (3*GFRAME)        // 30720

// ---------------- device scratch (bss) ----------------
__device__ float g_GI0[(size_t)TT * BB * G3];
__device__ float g_h0f[2][BB * HH];
__device__ float g_h1f[2][BB * HH];
__device__ __half g_h0h[2][BB*HH];              // fp16 state
__device__ __half g_h1h[2][BB*HH];
__device__ __half g_x1h[2][BB*HH];
__device__ __half g_Wh[3][(size_t)G3*HH];       // 0=Whh0 1=Wih1 2=Whh1 (pure fp16)
__device__ __half g_W0h[(size_t)G3*EE];         // Wih0
__device__ __half g_x0h[(size_t)TT*BB*EE];
// K-split donation buffers: 96 pairs x 256 threads x 24 floats
__device__ float g_part[96][256][24];
__device__ int   g_sflag[96];

// ---------------- helpers ----------------
__device__ __forceinline__ void cpa16(uint32_t dst, const void* src){
    asm volatile("cp.async.cg.shared.global [%0], [%1], 16;" :: "r"(dst), "l"(src));
}
__device__ __forceinline__ void cpa_commit(){ asm volatile("cp.async.commit_group;"); }
__device__ __forceinline__ void cpa_wait1(){ asm volatile("cp.async.wait_group 1;"); }

__device__ __forceinline__ void ldsm4(uint32_t* r, uint32_t a){
    asm volatile("ldmatrix.sync.aligned.m8n8.x4.shared.b16 {%0,%1,%2,%3}, [%4];"
        : "=r"(r[0]),"=r"(r[1]),"=r"(r[2]),"=r"(r[3]) : "r"(a));
}

#define MMA16816(c, a, b0, b1) \
    asm volatile("mma.sync.aligned.m16n8k16.row.col.f32.f16.f16.f32 " \
        "{%0,%1,%2,%3},{%4,%5,%6,%7},{%8,%9},{%0,%1,%2,%3};" \
        : "+f"((c)[0]),"+f"((c)[1]),"+f"((c)[2]),"+f"((c)[3]) \
        : "r"((a)[0]),"r"((a)[1]),"r"((a)[2]),"r"((a)[3]),"r"(b0),"r"(b1))

__device__ __forceinline__ float sigf(float v){ return 1.f/(1.f+__expf(-v)); }

// ---------------- init kernels ----------------
__global__ void zero_h_kernel() {
    int i = blockIdx.x*256 + threadIdx.x;  // grid 512 -> 131072 = BB*HH
    if (blockIdx.x == 0 && threadIdx.x < 96) g_sflag[threadIdx.x] = 0;
    g_h0f[0][i]=0.f; g_h1f[0][i]=0.f;
    __half z = __float2half(0.f);
    g_h0h[0][i]=z; g_h1h[0][i]=z;
}
__global__ void split_w_kernel(const float* __restrict__ w0, const float* __restrict__ w1,
                               const float* __restrict__ w2) {
    size_t i = (size_t)blockIdx.x*256 + threadIdx.x;
    int m = blockIdx.y;
    const float* s = (m==0)? w0 : (m==1)? w1 : w2;
    g_Wh[m][i] = __float2half_rn(s[i]);
}
__global__ void split_w0_kernel(const float* __restrict__ w) {
    size_t i = (size_t)blockIdx.x*256 + threadIdx.x;   // grid 6144
    g_W0h[i] = __float2half_rn(w[i]);
}
__global__ void split_x_kernel(const float* __restrict__ x) {
    size_t i = (size_t)blockIdx.x*256 + threadIdx.x;   // grid 65536
    g_x0h[i] = __float2half_rn(x[i]);
}

// ---------------- GI0 via pure fp16 mma ----------------
// grid (48, 512): x = 64-col block of G3 ; y = t*2 + mhalf. CTA = M64 x N64.
__global__ __launch_bounds__(128) void gi0_mma(
    const float* __restrict__ bias, const int* __restrict__ bs)
{
    extern __shared__ __align__(16) char smem[];
    const int nbase = blockIdx.x * 64;
    const int trow = blockIdx.y;
    const int t = trow >> 1, mb = (trow & 1) << 6;
    if (mb >= bs[t]) return;
    const int tid = threadIdx.x, wid = tid>>5, lane = tid&31;
    const int l4 = lane>>2, lm4 = lane&3;
    const size_t rowbase = (size_t)(t*BB + mb);

    float cc[8][4];
#pragma unroll
    for (int i=0;i<8;i++)
#pragma unroll
        for (int j=0;j<4;j++) cc[i][j]=0.f;

    const uint32_t smem_u = (uint32_t)__cvta_generic_to_shared(smem);
    const uint32_t a_off = (uint32_t)((wid*16 + (lane&15))*SA + (lane>>4)*16);
    const uint32_t b_off = (uint32_t)(((lane&7) + ((lane>>4)&1)*8)*SA + ((lane>>3)&1)*16);

    auto load_stage = [&](int s){
        const int k0 = s * KC;
        const uint32_t st = smem_u + (s % 3) * GFRAME;
#pragma unroll
        for (int i = 0; i < 2; i++) {   // A: 256 ops
            int cid = tid + i*128, r = cid>>2, c = cid&3;
            cpa16(st + r*SA + c*16, g_x0h + (rowbase+r)*EE + k0 + c*8);
        }
#pragma unroll
        for (int i = 0; i < 2; i++) {   // B: 256 ops
            int cid = tid + i*128, r = cid>>2, c = cid&3;
            cpa16(st + 5120 + r*SA + c*16, g_W0h + (size_t)(nbase+r)*EE + k0 + c*8);
        }
    };

    load_stage(0); cpa_commit();
    load_stage(1); cpa_commit();
    for (int s = 0; s < 16; s++) {
        cpa_wait1();
        __syncthreads();
        const uint32_t st = smem_u + (s % 3) * GFRAME;
        const uint32_t aB = st + a_off;
#pragma unroll
        for (int kc = 0; kc < 2; kc++) {
            uint32_t a[4];
            ldsm4(a, aB + kc*32);
#pragma unroll
            for (int g = 0; g < 4; g++) {
                uint32_t b[4];
                ldsm4(b, st + 5120 + (uint32_t)(g*16*SA) + b_off + kc*32);
                MMA16816(cc[2*g],   a, b[0], b[1]);
                MMA16816(cc[2*g+1], a, b[2], b[3]);
            }
        }
        if (s+2 < 16) load_stage(s+2);
        cpa_commit();
    }

#pragma unroll
    for (int nt = 0; nt < 8; nt++) {
        int n = nbase + nt*8 + lm4*2;
        float2 bv = *(const float2*)&bias[n];
#pragma unroll
        for (int rr = 0; rr < 2; rr++) {
            size_t row = rowbase + wid*16 + l4 + rr*8;
            float2 o; o.x = cc[nt][rr*2] + bv.x; o.y = cc[nt][rr*2+1] + bv.y;
            *(float2*)&g_GI0[row*G3 + n] = o;
        }
    }
}

// ---------------- pure fp16 mma step with K-split donation ----------------
// CTAs [0,64):   layer0 @ t=kk : M64 x 32 hidden cols
// CTAs [64,192): layer1 @ t=kk-1 : M64 x 16 hidden cols, dual GEMM (warp-split)
// When bs[t] <= 64: odd-idx CTA computes K[512:1024) of the even partner's tile.
__global__ __launch_bounds__(256, 2) void mma_step(
    const float* __restrict__ bhh0, const float* __restrict__ bih1,
    const float* __restrict__ bhh1, const int* __restrict__ bs, int kk)
{
    extern __shared__ __align__(16) char smem[];
    const int cta = blockIdx.x;
    const bool l1 = cta >= 64;
    const int t = l1 ? kk-1 : kk;
    if (t < 0 || t >= TT) return;
    const int p = t & 1;
    const int idx = l1 ? cta-64 : cta;
    const int jbase = l1 ? (idx>>1)*16 : (idx>>1)*32;
    const int mbase = (idx&1)*64;
    const int tid = threadIdx.x, wid = tid>>5, lane = tid&31;
    const int l4 = lane>>2, lm4 = lane&3;
    const int mi = wid & 3;
    const int ws = wid >> 2;            // l0: n-half ; l1: gemm select (0=gh,1=gi)
    const int active = bs[t];
    const int NCOL = l1 ? 16 : 32;
    const int pid = cta >> 1;           // pair id 0..95

    const bool split   = (active <= 64);
    const bool partner = split && (idx & 1);   // donates K-half to even neighbor
    const int  mbase_c = split ? 0 : mbase;    // compute m-tile

    const float* hpf_all = l1 ? g_h1f[p] : g_h0f[p];
    float* hnf_all = l1 ? g_h1f[p^1] : g_h0f[p^1];
    __half* hh_all = l1 ? g_h1h[p^1] : g_h0h[p^1];

    if (partner) {
        // my own m-tile (rows 64..127) is inactive: pass h through unchanged
        const int tot = 64*NCOL;
        for (int i = tid; i < tot; i += 256) {
            int r = i / NCOL, c = i % NCOL;
            size_t off = (size_t)(64 + r)*HH + jbase + c;
            float hv = hpf_all[off];
            hnf_all[off] = hv;
            hh_all[off] = __float2half_rn(hv);
        }
        // then fall through: compute partner K-half for rows 0..63
    }

    const __half *Ah, *Wh, *Ai, *Wi;
    if (!l1) {
        Ah = g_h0h[p]; Wh = g_Wh[0];
        Ai = nullptr;  Wi = nullptr;
    } else {
        Ah = g_h1h[p]; Wh = g_Wh[2];
        Ai = g_x1h[p]; Wi = g_Wh[1];
    }

    const uint32_t smem_u = (uint32_t)__cvta_generic_to_shared(smem);

    auto load_stage = [&](int s){
        const int k0 = s * KC;
        const uint32_t st = smem_u + (s % DEPTH) * FRAME;
        if (!l1) {
            {   // A: 256 ops (1/thread)
                int r = tid>>2, c = tid&3;
                cpa16(st + r*SA + c*16, Ah + (size_t)(mbase_c+r)*HH + k0 + c*8);
            }
            // B: 96 rows x 4 = 384 ops
#pragma unroll
            for (int i = 0; i < 2; i++) {
                int cid = tid + i*256;
                if (cid < 384) {
                    int r = cid>>2, c = cid&3;
                    int wrow = (r>>5)*HH + jbase + (r&31);
                    cpa16(st + 5120 + r*SA + c*16, Wh + (size_t)wrow*HH + k0 + c*8);
                }
            }
        } else {
            // A: AH + AI tiles, 256 each = 512 ops (2/thread)
#pragma unroll
            for (int i = 0; i < 2; i++) {
                int cid = tid + i*256, tile = cid>>8, rr = cid&255;
                int r = rr>>2, c = rr&3;
                const __half* A = tile ? Ai : Ah;
                cpa16(st + tile*5120 + r*SA + c*16, A + (size_t)(mbase_c+r)*HH + k0 + c*8);
            }
            // B: WH + WI tiles, 192 each = 384 ops
#pragma unroll
            for (int i = 0; i < 2; i++) {
                int cid = tid + i*256;
                if (cid < 384) {
                    int tile = cid/192, rr = cid%192;
                    int r = rr>>2, c = rr&3;
                    int wrow = (r>>4)*HH + jbase + (r&15);
                    const __half* W = tile ? Wi : Wh;
                    cpa16(st + 10240 + tile*3840 + r*SA + c*16, W + (size_t)wrow*HH + k0 + c*8);
                }
            }
        }
    };

    float acc[6][4];
#pragma unroll
    for (int i=0;i<6;i++)
#pragma unroll
        for (int j=0;j<4;j++) acc[i][j]=0.f;

    const uint32_t a_off = (uint32_t)((mi*16 + (lane&15))*SA + (lane>>4)*16);
    const uint32_t b_off = (uint32_t)(((lane&7) + ((lane>>4)&1)*8)*SA + ((lane>>3)&1)*16);

    // stage range: owner of a split pair does K[0:512), partner K[512:1024)
    const int sBeg = partner ? (NSTG/2) : 0;
    const int sEnd = (split && !partner) ? (NSTG/2) : NSTG;

    load_stage(sBeg);   cpa_commit();
    load_stage(sBeg+1); cpa_commit();
    for (int s = sBeg; s < sEnd; s++) {
        cpa_wait1();
        __syncthreads();
        const uint32_t st = smem_u + (s % DEPTH) * FRAME;
        if (!l1) {
            const uint32_t aB = st + a_off;
            const uint32_t grp = (uint32_t)(ws*16*SA);
#pragma unroll
            for (int kc = 0; kc < 2; kc++) {
                uint32_t a[4];
                ldsm4(a, aB + kc*32);
#pragma unroll
                for (int g = 0; g < 3; g++) {
                    uint32_t b[4];
                    ldsm4(b, st + 5120 + (uint32_t)(g*32*SA) + grp + b_off + kc*32);
                    MMA16816(acc[2*g],   a, b[0], b[1]);
                    MMA16816(acc[2*g+1], a, b[2], b[3]);
                }
            }
        } else {
            const uint32_t aB = st + (ws?5120:0) + a_off;
            const uint32_t bBase = st + 10240 + (ws?3840:0);
#pragma unroll
            for (int kc = 0; kc < 2; kc++) {
                uint32_t a[4];
                ldsm4(a, aB + kc*32);
#pragma unroll
                for (int g = 0; g < 3; g++) {
                    uint32_t b[4];
                    ldsm4(b, bBase + (uint32_t)(g*16*SA) + b_off + kc*32);
                    MMA16816(acc[2*g],   a, b[0], b[1]);
                    MMA16816(acc[2*g+1], a, b[2], b[3]);
                }
            }
        }
        if (s+2 < sEnd) load_stage(s+2);
        cpa_commit();
    }

    // ---- partner: publish raw accumulators, signal, done ----
    if (partner) {
        float* dst = &g_part[pid][tid][0];
#pragma unroll
        for (int i = 0; i < 6; i++)
#pragma unroll
            for (int j = 0; j < 4; j++) dst[i*4+j] = acc[i][j];
        __threadfence();
        __syncthreads();
        if (tid == 0) {
            int v = kk + 1;
            asm volatile("st.release.gpu.s32 [%0], %1;" :: "l"(&g_sflag[pid]), "r"(v) : "memory");
        }
        return;
    }

    // ---- l1: exchange gi accumulators to gh warps via smem ----
    float ci[6][4];
    if (l1) {
        __syncthreads();   // ensure no warp still reads the frame smem bytes
        float* xch = (float*)smem;
        if (ws == 1) {
            float* dst = xch + (size_t)(mi*32 + lane)*24;
#pragma unroll
            for (int i = 0; i < 6; i++)
#pragma unroll
                for (int j = 0; j < 4; j++) dst[i*4+j] = acc[i][j];
        }
        __syncthreads();
        if (ws == 0) {
            const float* src = xch + (size_t)(mi*32 + lane)*24;
#pragma unroll
            for (int i = 0; i < 6; i++)
#pragma unroll
                for (int j = 0; j < 4; j++) ci[i][j] = src[i*4+j];
        } else {
            return;   // gi warps done
        }
    }

    // ---- split owner: wait for partner's K-half and fold it in ----
    if (split) {
        const int tgt = kk + 1;
        int v;
        do {
            asm volatile("ld.acquire.gpu.s32 %0, [%1];" : "=r"(v)
                         : "l"((const int*)&g_sflag[pid]) : "memory");
        } while (v < tgt);
        const float* ph = &g_part[pid][tid][0];
#pragma unroll
        for (int i = 0; i < 6; i++)
#pragma unroll
            for (int j = 0; j < 4; j++) acc[i][j] += ph[i*4+j];
        if (l1) {
            const float* pi2 = &g_part[pid][tid+128][0];
#pragma unroll
            for (int i = 0; i < 6; i++)
#pragma unroll
                for (int j = 0; j < 4; j++) ci[i][j] += pi2[i*4+j];
        }
    }

    // ---- epilogue (R8-proven gate math), rows mbase_c..mbase_c+63 ----
    const int m0 = mbase_c + mi*16 + l4;
    const int jw = l1 ? jbase : (jbase + ws*16);
    const float* bh = l1 ? bhh1 : bhh0;
#pragma unroll
    for (int c = 0; c < 2; c++) {
        const int j = jw + c*8 + lm4*2;
        float2 bhr = *(const float2*)(bh + j);
        float2 bhz = *(const float2*)(bh + HH + j);
        float2 bhn = *(const float2*)(bh + 2*HH + j);
        float2 bir, biz, bin;
        if (l1) {
            bir = *(const float2*)(bih1 + j);
            biz = *(const float2*)(bih1 + HH + j);
            bin = *(const float2*)(bih1 + 2*HH + j);
        }
        const int rg = c, zg = 2 + c, ng = 4 + c;
#pragma unroll
        for (int rr = 0; rr < 2; rr++) {
            const int m = m0 + rr*8;
            const bool keep = m < active;
            float gr0,gr1,gz0,gz1,gn0,gn1;
            if (!l1) {
                const float* gp = g_GI0 + (size_t)(t*BB + m)*G3;
                float2 a = *(const float2*)(gp + j);
                float2 b = *(const float2*)(gp + HH + j);
                float2 cc2 = *(const float2*)(gp + 2*HH + j);
                gr0=a.x; gr1=a.y; gz0=b.x; gz1=b.y; gn0=cc2.x; gn1=cc2.y;
            } else {
                gr0 = ci[rg][rr*2] + bir.x;  gr1 = ci[rg][rr*2+1] + bir.y;
                gz0 = ci[zg][rr*2] + biz.x;  gz1 = ci[zg][rr*2+1] + biz.y;
                gn0 = ci[ng][rr*2] + bin.x;  gn1 = ci[ng][rr*2+1] + bin.y;
            }
            float hr0 = acc[rg][rr*2] + bhr.x, hr1 = acc[rg][rr*2+1] + bhr.y;
            float hz0 = acc[zg][rr*2] + bhz.x, hz1 = acc[zg][rr*2+1] + bhz.y;
            float hn0 = acc[ng][rr*2] + bhn.x, hn1 = acc[ng][rr*2+1] + bhn.y;

            size_t off = (size_t)m*HH + j;
            float2 hp = *(const float2*)(hpf_all + off);

            float r0 = sigf(gr0+hr0), z0 = sigf(gz0+hz0);
            float nv0 = tanhf(fmaf(r0, hn0, gn0));
            float hv0 = fmaf(z0, hp.x - nv0, nv0);
            float r1 = sigf(gr1+hr1), z1 = sigf(gz1+hz1);
            float nv1 = tanhf(fmaf(r1, hn1, gn1));
            float hv1 = fmaf(z1, hp.y - nv1, nv1);

            float kv0 = keep ? hv0 : hp.x;
            float kv1 = keep ? hv1 : hp.y;

            float2 outv; outv.x = kv0; outv.y = kv1;
            *(float2*)(hnf_all + off) = outv;
            __half2 vh;
            vh.x = __float2half_rn(kv0);
            vh.y = __float2half_rn(kv1);
            *(__half2*)(hh_all + off) = vh;
            if (!l1) {
                // layer1 input = UNMASKED hn
                __half2 xh;
                xh.x = __float2half_rn(hv0);
                xh.y = __float2half_rn(hv1);
                *(__half2*)(g_x1h[p] + off) = xh;
            }
        }
    }
}

// ---------------- final gather ----------------
__global__ void gather_kernel(const int* __restrict__ u, float* __restrict__ out) {
    int idx = blockIdx.x*blockDim.x + threadIdx.x;
    int l = idx / (BB*(HH/4));
    int rem = idx % (BB*(HH/4));
    int b = rem / (HH/4), j4 = rem % (HH/4);
    const float* src = (l ? g_h1f[0] : g_h0f[0]) + (size_t)u[b]*HH;
    ((float4*)out)[idx] = ((const float4*)src)[j4];
}

// ---------------------------------------------------------------------------
extern "C" void kernel_launch(void* const* d_in, const int* in_sizes, int n_in,
                              void* d_out, int out_size) {
    const float* x    = (const float*)d_in[0];
    const float* Wih0 = (const float*)d_in[1];
    const float* Whh0 = (const float*)d_in[2];
    const float* bih0 = (const float*)d_in[3];
    const float* bhh0 = (const float*)d_in[4];
    const float* Wih1 = (const float*)d_in[5];
    const float* Whh1 = (const float*)d_in[6];
    const float* bih1 = (const float*)d_in[7];
    const float* bhh1 = (const float*)d_in[8];
    const int*   bs   = (const int*)d_in[9];
    const int*   ui   = (const int*)d_in[10];

    cudaFuncSetAttribute(mma_step, cudaFuncAttributeMaxDynamicSharedMemorySize, SMEM_DYN);
    cudaFuncSetAttribute(gi0_mma, cudaFuncAttributeMaxDynamicSharedMemorySize, GSMEM);

    zero_h_kernel<<<512, 256>>>();
    split_w_kernel<<<dim3((G3*HH)/256, 3), 256>>>(Whh0, Wih1, Whh1);
    split_w0_kernel<<<(G3*EE)/256, 256>>>(Wih0);
    split_x_kernel<<<(TT*BB*EE)/256, 256>>>(x);
    gi0_mma<<<dim3(48, 2*TT), 128, GSMEM>>>(bih0, bs);
    for (int k = 0; k <= TT; k++)
        mma_step<<<192, 256, SMEM_DYN>>>(bhh0, bih1, bhh1, bs, k);
    gather_kernel<<<256, 256>>>(ui, (float*)d_out);
}